// round 13
// baseline (speedup 1.0000x reference)
#include <cuda_runtime.h>
#include <math.h>
#include <stdint.h>

#define B_ 32
#define L_ 256
#define A_ 20
#define NTHR 736            // 20 consumer + pair + const (workers=704 thr) + producer warp
#define TS 16               // tiles per stage
#define NSTAGE 16           // 256 tiles / 16
#define STAGE_F 6400
#define STAGE_BYTES 25600

__device__ double g_res[L_][3];          // per-i {lse_sum, pair_sum, reg_sum}
__device__ unsigned int g_bcount = 0;    // reset by last block each launch

// smem layout (bytes):
//   0      .. 102400  ring: 4 slots x 25600 (even stages->slots 0/2 via bulk,
//                     odd stages->slots 1/3 via LDGSTS)
//   102400 .. 110592  xpk uint32[16 sidx][32 b][4 g]: bytes 4*x[b][p]
//   110592 .. 110720  xi[32]
//   110720 .. 110800  wsrow[20]
//   110800 .. 110880  csts[20]
//   110880 .. 110960  sredr[20]
//   110960 .. 110964  pairv
//   110968 .. 111032  mbarriers: slot r at +r*16 (full +0, empty +8)
//   111032 .. 111036  amLast
// epilogue reuse: lgbuf f32[32*21] @0, dred double[96] @byte 4096
#define SMEM_BYTES 111040
#define MB_OFF 110968

__device__ __forceinline__ uint32_t smem_u32(const void* p) {
    uint32_t a;
    asm("{ .reg .u64 t; cvta.to.shared.u64 t, %1; cvt.u32.u64 %0, t; }" : "=r"(a) : "l"(p));
    return a;
}
#define MB_INIT(addr, cnt) \
    asm volatile("mbarrier.init.shared.b64 [%0], %1;" :: "r"(addr), "r"(cnt) : "memory")
#define MB_EXPECT_TX(addr, bytes) \
    asm volatile("mbarrier.arrive.expect_tx.shared.b64 _, [%0], %1;" :: "r"(addr), "r"(bytes) : "memory")
#define MB_ARRIVE(addr) \
    asm volatile("mbarrier.arrive.shared.b64 _, [%0];" :: "r"(addr) : "memory")
#define CP_COMMIT() asm volatile("cp.async.commit_group;" ::: "memory")
#define BAR1() asm volatile("bar.sync 1, 704;" ::: "memory")

__device__ __forceinline__ void mb_wait_acq(uint32_t mbar, uint32_t parity) {
    asm volatile(
        "{\n\t.reg .pred P;\n\t"
        "WL_%=:\n\t"
        "mbarrier.try_wait.parity.acquire.cta.shared::cta.b64 P, [%0], %1, 0x989680;\n\t"
        "@P bra.uni WD_%=;\n\t"
        "bra.uni WL_%=;\n\t"
        "WD_%=:\n\t}"
        :: "r"(mbar), "r"(parity) : "memory");
}
__device__ __forceinline__ void mb_wait_rlx(uint32_t mbar, uint32_t parity) {
    asm volatile(
        "{\n\t.reg .pred P;\n\t"
        "WL_%=:\n\t"
        "mbarrier.try_wait.parity.relaxed.cta.shared::cta.b64 P, [%0], %1, 0x989680;\n\t"
        "@P bra.uni WD_%=;\n\t"
        "bra.uni WL_%=;\n\t"
        "WD_%=:\n\t}"
        :: "r"(mbar), "r"(parity) : "memory");
}
__device__ __forceinline__ void bulk_g2s(uint32_t dst, const void* src,
                                         uint32_t bytes, uint32_t mbar) {
    asm volatile(
        "cp.async.bulk.shared::cta.global.mbarrier::complete_tx::bytes [%0], [%1], %2, [%3];"
        :: "r"(dst), "l"(src), "r"(bytes), "r"(mbar) : "memory");
}
__device__ __forceinline__ void ldgsts16(uint32_t dst, const void* src) {
    asm volatile("cp.async.cg.shared.global [%0], [%1], 16;"
                 :: "r"(dst), "l"(src) : "memory");
}

__global__ __launch_bounds__(NTHR, 2) void mrf_kernel(const int* __restrict__ x,
                                                      const float* __restrict__ ws,
                                                      const float* __restrict__ wp,
                                                      float* __restrict__ out) {
    extern __shared__ char smem_raw[];
    float*        bufs  = reinterpret_cast<float*>(smem_raw);
    uint32_t*     xpk   = reinterpret_cast<uint32_t*>(smem_raw + 102400);
    int*          xi    = reinterpret_cast<int*>(smem_raw + 110592);
    float*        wsrow = reinterpret_cast<float*>(smem_raw + 110720);
    float*        csts  = reinterpret_cast<float*>(smem_raw + 110800);
    float*        sredr = reinterpret_cast<float*>(smem_raw + 110880);
    float*        pairv = reinterpret_cast<float*>(smem_raw + 110960);
    int*          amLast= reinterpret_cast<int*>(smem_raw + 111032);
    const uint32_t mb0  = smem_u32(smem_raw + MB_OFF);
    const uint32_t bufa = smem_u32(smem_raw);

    const int i    = blockIdx.x;
    const int tid  = threadIdx.x;
    const int wid  = tid >> 5;
    const int lane = tid & 31;
    const char* srci = reinterpret_cast<const char*>(wp) + (size_t)i * 409600;

    // LDGSTS prologue FIRST: workers collectively prefetch odd stages 1 and 3.
    if (tid < 704) {
        for (int n = tid; n < 1600; n += 704)
            ldgsts16(bufa + 1 * STAGE_BYTES + n * 16, srci + 1 * STAGE_BYTES + n * 16);
        CP_COMMIT();
        for (int n = tid; n < 1600; n += 704)
            ldgsts16(bufa + 3 * STAGE_BYTES + n * 16, srci + 3 * STAGE_BYTES + n * 16);
        CP_COMMIT();
    }

    // mbarriers: full count 1 (tx-based), empty count 22 (worker warps' lane0).
    if (tid == 0) {
        for (int r = 0; r < 4; r++) {
            MB_INIT(mb0 + r * 16, 1);
            MB_INIT(mb0 + r * 16 + 8, 22);
        }
    }

    // Pack x bytes (pre-scaled by 4): xpk[(sidx*32+b)*4+g] = 4*x[b][sidx*16+4g..+3]
    const int4* x4 = reinterpret_cast<const int4*>(x);
    for (int n = tid; n < 2048; n += NTHR) {
        int sidx = n >> 7, rem = n & 127;
        int b = rem >> 2, g = rem & 3;
        int4 q = x4[b * 64 + sidx * 4 + g];
        xpk[n] = (uint32_t)(q.x << 2) | ((uint32_t)(q.y << 2) << 8) |
                 ((uint32_t)(q.z << 2) << 16) | ((uint32_t)(q.w << 2) << 24);
    }
    if (tid < B_) xi[tid] = x[tid * L_ + i];
    if (tid >= 32 && tid < 52) wsrow[tid - 32] = ws[i * A_ + (tid - 32)];
    asm volatile("fence.proxy.async.shared::cta;" ::: "memory");
    __syncthreads();

    float acc = 0.f, pair = 0.f, c_acc = 0.f, reg1 = 0.f, reg2 = 0.f;

    if (wid == 22) {
        // ---- Producer (lane 0): bulk copies for even stages into slots 0/2 ----
        if (lane == 0) {
            for (int u = 0; u < 8; u++) {
                int stage = 2 * u, slot = stage & 3;
                if (u >= 2) mb_wait_rlx(mb0 + slot * 16 + 8, ((u - 2) >> 1) & 1);
                MB_EXPECT_TX(mb0 + slot * 16, STAGE_BYTES);
                bulk_g2s(bufa + slot * STAGE_BYTES, srci + (size_t)stage * STAGE_BYTES,
                         STAGE_BYTES, mb0 + slot * 16);
            }
        }
    } else {
        // ---- Workers: 20 consumer warps (j=wid), pair warp (20), const warp (21) ----
        const uint4* xpk4 = reinterpret_cast<const uint4*>(xpk);
        const float4* b4all = reinterpret_cast<const float4*>(smem_raw);
        const float2* b2all = reinterpret_cast<const float2*>(smem_raw);
        const char* btj0 = smem_raw + wid * 80;            // consumers: row j
        const char* btp0 = (wid == 20) ? smem_raw + xi[lane] * 80 : smem_raw;
        const int j20 = lane * 20;                          // const warp row

        for (int s = 0; s < NSTAGE; s++) {
            const int slot = s & 3;
            if ((s & 1) == 0) {
                mb_wait_acq(mb0 + slot * 16, (s >> 2) & 1);
            } else {
                if (s <= 12) asm volatile("cp.async.wait_group 1;" ::: "memory");
                else         asm volatile("cp.async.wait_group 0;" ::: "memory");
                BAR1();
            }

            // ---- consume stage s from ring slot ----
            const int pbase = s * TS;
            if (wid < 20) {
                // reg pass: 10 floats (2 LDS.128 + 1 LDS.64); tid < 640 here
                float4 q1 = b4all[slot * 1600 + tid];
                float4 q2 = b4all[slot * 1600 + 640 + tid];
                float2 t2 = b2all[slot * 3200 + 2560 + tid];
                reg1 += fabsf(q1.x); reg2 = fmaf(q1.x, q1.x, reg2);
                reg1 += fabsf(q1.y); reg2 = fmaf(q1.y, q1.y, reg2);
                reg1 += fabsf(q1.z); reg2 = fmaf(q1.z, q1.z, reg2);
                reg1 += fabsf(q1.w); reg2 = fmaf(q1.w, q1.w, reg2);
                reg1 += fabsf(q2.x); reg2 = fmaf(q2.x, q2.x, reg2);
                reg1 += fabsf(q2.y); reg2 = fmaf(q2.y, q2.y, reg2);
                reg1 += fabsf(q2.z); reg2 = fmaf(q2.z, q2.z, reg2);
                reg1 += fabsf(q2.w); reg2 = fmaf(q2.w, q2.w, reg2);
                reg1 += fabsf(t2.x); reg2 = fmaf(t2.x, t2.x, reg2);
                reg1 += fabsf(t2.y); reg2 = fmaf(t2.y, t2.y, reg2);

                if (pbase + TS - 1 > i) {
                    const char* bj = btj0 + slot * STAGE_BYTES;
                    const uint4 u = xpk4[s * 32 + lane];
                    const uint32_t wv[4] = {u.x, u.y, u.z, u.w};
                    if (pbase > i) {
#pragma unroll
                        for (int k = 0; k < TS; k++) {
                            uint32_t e4 = __byte_perm(wv[k >> 2], 0, 0x4440 | (k & 3));
                            acc += *reinterpret_cast<const float*>(bj + k * 1600 + e4);
                        }
                    } else {
#pragma unroll
                        for (int k = 0; k < TS; k++) {
                            if (pbase + k > i) {
                                uint32_t e4 = __byte_perm(wv[k >> 2], 0, 0x4440 | (k & 3));
                                acc += *reinterpret_cast<const float*>(bj + k * 1600 + e4);
                            }
                        }
                    }
                }
            } else if (wid == 20) {
                const char* bp = btp0 + slot * STAGE_BYTES;
                const uint4 u = xpk4[s * 32 + lane];
                const uint32_t wv[4] = {u.x, u.y, u.z, u.w};
#pragma unroll
                for (int k = 0; k < TS; k++) {
                    uint32_t e4 = __byte_perm(wv[k >> 2], 0, 0x4440 | (k & 3));
                    pair += *reinterpret_cast<const float*>(bp + k * 1600 + e4);
                }
            } else {   // wid == 21: const warp
                if (lane < 20 && pbase <= i) {
                    const float* bf = bufs + slot * STAGE_F;
                    int tmax = i - pbase;
                    int lim = tmax < TS ? tmax : TS;
                    for (int t = 0; t < lim; t++) c_acc += bf[t * 400 + j20 + 19];
                    if (tmax < TS) c_acc += bf[tmax * 400 + j20 + lane];
                }
            }

            // ---- post-consume signaling / next-stage issue ----
            if ((s & 1) == 0) {
                if (lane == 0) MB_ARRIVE(mb0 + slot * 16 + 8);
            } else {
                BAR1();    // everyone done reading slot before overwrite
                if (s <= 11) {
                    const char* src = srci + (size_t)(s + 4) * STAGE_BYTES;
                    for (int n = tid; n < 1600; n += 704)
                        ldgsts16(bufa + slot * STAGE_BYTES + n * 16, src + n * 16);
                    CP_COMMIT();
                }
            }
        }
    }

    // ---------------- Epilogue ----------------
    __syncthreads();
    if (wid < 20) {
        float rv = reg1 + reg2;
#pragma unroll
        for (int o = 16; o > 0; o >>= 1) rv += __shfl_down_sync(0xffffffffu, rv, o);
        if (lane == 0) sredr[wid] = rv;
    }
    if (wid == 20) {
        float pv = pair;
#pragma unroll
        for (int o = 16; o > 0; o >>= 1) pv += __shfl_down_sync(0xffffffffu, pv, o);
        if (lane == 0) pairv[0] = pv;
    }
    if (wid == 21 && lane < 20) csts[lane] = c_acc;
    __syncthreads();

    if (wid < 20) bufs[lane * 21 + wid] = acc + csts[wid] + wsrow[wid];  // lgbuf[b*21+j]
    if (tid == 704) g_res[i][1] = (double)pairv[0];
    __syncthreads();

    if (tid < 32) {       // lse per b, minus single
        const float* row = &bufs[tid * 21];
        float m = row[0];
#pragma unroll
        for (int jj = 1; jj < A_; jj++) m = fmaxf(m, row[jj]);
        float se = 0.f;
#pragma unroll
        for (int jj = 0; jj < A_; jj++) se += __expf(row[jj] - m);
        float lse = m + __logf(se);
        double val = (double)lse - (double)wsrow[xi[tid]];
#pragma unroll
        for (int o = 16; o > 0; o >>= 1) val += __shfl_down_sync(0xffffffffu, val, o);
        if (tid == 0) g_res[i][0] = val;
    } else if (tid < 64) {   // reg sum over 20 consumer warps
        double rv = (lane < 20) ? (double)sredr[lane] : 0.0;
#pragma unroll
        for (int o = 16; o > 0; o >>= 1) rv += __shfl_down_sync(0xffffffffu, rv, o);
        if (lane == 0) g_res[i][2] = rv;
    }
    __syncthreads();

    // ---- Fused deterministic final reduction (last CTA) ----
    if (tid == 0) {
        __threadfence();
        *amLast = (atomicAdd(&g_bcount, 1u) == (unsigned)(gridDim.x - 1)) ? 1 : 0;
    }
    __syncthreads();
    if (!*amLast) return;
    __threadfence();

    double LS = 0.0, PA = 0.0, RP = 0.0, RS = 0.0;
    if (tid < L_) { LS = g_res[tid][0]; PA = g_res[tid][1]; RP = g_res[tid][2]; }
    for (int n = tid; n < L_ * A_; n += NTHR) {
        float w = ws[n];
        RS += (double)fabsf(w) + (double)w * (double)w;
    }
    double* dred = reinterpret_cast<double*>(smem_raw + 4096);
#pragma unroll
    for (int o = 16; o > 0; o >>= 1) {
        LS += __shfl_down_sync(0xffffffffu, LS, o);
        PA += __shfl_down_sync(0xffffffffu, PA, o);
        RP += __shfl_down_sync(0xffffffffu, RP, o);
        RS += __shfl_down_sync(0xffffffffu, RS, o);
    }
    if (lane == 0) {
        dred[wid] = LS; dred[24 + wid] = PA; dred[48 + wid] = RP; dred[72 + wid] = RS;
    }
    __syncthreads();
    if (tid == 0) {
        double ls = 0, pa = 0, rp = 0, rs = 0;
        for (int w = 0; w < 23; w++) {
            ls += dred[w]; pa += dred[24 + w]; rp += dred[48 + w]; rs += dred[72 + w];
        }
        // LAMBDA_SINGLE = 1.0, LAMBDA_PAIR = 0.2*(L-1) = 51.0
        out[0] = (float)((ls - pa) / (double)B_ + 1.0 * rs + 51.0 * rp);
        g_bcount = 0;   // self-reset for graph replay
    }
}

extern "C" void kernel_launch(void* const* d_in, const int* in_sizes, int n_in,
                              void* d_out, int out_size) {
    (void)in_sizes; (void)n_in; (void)out_size;
    const int*   x  = (const int*)d_in[0];
    const float* ws = (const float*)d_in[1];
    const float* wp = (const float*)d_in[2];
    float* out = (float*)d_out;

    cudaFuncSetAttribute(mrf_kernel, cudaFuncAttributeMaxDynamicSharedMemorySize, SMEM_BYTES);
    mrf_kernel<<<L_, NTHR, SMEM_BYTES>>>(x, ws, wp, out);
}

// round 14
// speedup vs baseline: 1.0485x; 1.0485x over previous
#include <cuda_runtime.h>
#include <math.h>
#include <stdint.h>

#define B_ 32
#define L_ 256
#define A_ 20
#define NTHR 256            // 5 consumer warps + pair + const + producer
#define TS 8                // tiles per stage
#define RING 2
#define NSTAGE 8            // 64 tiles per quarter / 8
#define STAGE_F 3200
#define STAGE_BYTES 12800

__device__ float g_lg[L_][4][662];        // per (i,q): 640 acc, 20 const, pair, reg
__device__ unsigned int g_icount[L_];     // per-i arrival counters (self-reset)
__device__ unsigned int g_bcount = 0;     // combiner counter (self-reset)
__device__ double g_res[L_][3];           // per-i {lse_sum, pair_sum, reg_sum}

// smem layout (bytes):
//   0     .. 25600  ring data (2 x 12800), row-major tiles
//   25600 .. 27648  xpk uint32[8 sidx][32 b][2 g]: bytes 4*x[b][p]
//   27648 .. 27776  xi[32]
//   27776 .. 27856  wsrow[20]
//   27856 .. 27888  sredr[5] (+pad)
//   27888 .. 27892  pairv
//   27896 .. 27928  mbarriers per r (stride 16): full +0, empty +8
//   27928 .. 27936  flags[2]
// combiner reuse: lgbuf f32[32*21] @0, csts f32[20] @3072, dred double[32] @4096
#define SMEM_BYTES 27936
#define MB_OFF 27896

__device__ __forceinline__ uint32_t smem_u32(const void* p) {
    uint32_t a;
    asm("{ .reg .u64 t; cvta.to.shared.u64 t, %1; cvt.u32.u64 %0, t; }" : "=r"(a) : "l"(p));
    return a;
}
#define MB_INIT(addr, cnt) \
    asm volatile("mbarrier.init.shared.b64 [%0], %1;" :: "r"(addr), "r"(cnt) : "memory")
#define MB_EXPECT_TX(addr, bytes) \
    asm volatile("mbarrier.arrive.expect_tx.shared.b64 _, [%0], %1;" :: "r"(addr), "r"(bytes) : "memory")
#define MB_ARRIVE(addr) \
    asm volatile("mbarrier.arrive.shared.b64 _, [%0];" :: "r"(addr) : "memory")

__device__ __forceinline__ void mb_wait_acq(uint32_t mbar, uint32_t parity) {
    asm volatile(
        "{\n\t.reg .pred P;\n\t"
        "WL_%=:\n\t"
        "mbarrier.try_wait.parity.acquire.cta.shared::cta.b64 P, [%0], %1, 0x989680;\n\t"
        "@P bra.uni WD_%=;\n\t"
        "bra.uni WL_%=;\n\t"
        "WD_%=:\n\t}"
        :: "r"(mbar), "r"(parity) : "memory");
}
__device__ __forceinline__ void mb_wait_rlx(uint32_t mbar, uint32_t parity) {
    asm volatile(
        "{\n\t.reg .pred P;\n\t"
        "WL_%=:\n\t"
        "mbarrier.try_wait.parity.relaxed.cta.shared::cta.b64 P, [%0], %1, 0x989680;\n\t"
        "@P bra.uni WD_%=;\n\t"
        "bra.uni WL_%=;\n\t"
        "WD_%=:\n\t}"
        :: "r"(mbar), "r"(parity) : "memory");
}
__device__ __forceinline__ void bulk_g2s(uint32_t dst, const void* src,
                                         uint32_t bytes, uint32_t mbar) {
    asm volatile(
        "cp.async.bulk.shared::cta.global.mbarrier::complete_tx::bytes [%0], [%1], %2, [%3];"
        :: "r"(dst), "l"(src), "r"(bytes), "r"(mbar) : "memory");
}

__global__ __launch_bounds__(NTHR, 7) void mrf_kernel(const int* __restrict__ x,
                                                      const float* __restrict__ ws,
                                                      const float* __restrict__ wp,
                                                      float* __restrict__ out) {
    extern __shared__ char smem_raw[];
    float*        bufs  = reinterpret_cast<float*>(smem_raw);
    uint32_t*     xpk   = reinterpret_cast<uint32_t*>(smem_raw + 25600);
    int*          xi    = reinterpret_cast<int*>(smem_raw + 27648);
    float*        wsrow = reinterpret_cast<float*>(smem_raw + 27776);
    float*        sredr = reinterpret_cast<float*>(smem_raw + 27856);
    float*        pairv = reinterpret_cast<float*>(smem_raw + 27888);
    int*          flags = reinterpret_cast<int*>(smem_raw + 27928);
    float*        cstsc = reinterpret_cast<float*>(smem_raw + 3072);   // combiner only
    const uint32_t mb0  = smem_u32(smem_raw + MB_OFF);
    const uint32_t bufa = smem_u32(smem_raw);

    const int i    = blockIdx.x;
    const int q    = blockIdx.y;          // quarter: p in [q*64, q*64+64)
    const int tid  = threadIdx.x;
    const int wid  = tid >> 5;
    const int lane = tid & 31;

    // full: tx-based (count 1). empty: 7 arrivals (5 consumers + pair + const).
    if (tid == 0) {
        for (int r = 0; r < RING; r++) {
            MB_INIT(mb0 + r * 16, 1);
            MB_INIT(mb0 + r * 16 + 8, 7);
        }
    }

    // Pack x bytes (pre-scaled by 4): xpk[sidx*64 + b*2 + g] = bytes of
    // 4*x[b][p], p = q*64 + sidx*8 + 4g .. +3
    const int4* x4 = reinterpret_cast<const int4*>(x);
    for (int n = tid; n < 512; n += NTHR) {
        int sidx = n >> 6, rem = n & 63;
        int b = rem >> 1, g = rem & 1;
        int4 qq = x4[b * 64 + q * 16 + sidx * 2 + g];
        xpk[n] = (uint32_t)(qq.x << 2) | ((uint32_t)(qq.y << 2) << 8) |
                 ((uint32_t)(qq.z << 2) << 16) | ((uint32_t)(qq.w << 2) << 24);
    }
    if (tid < B_) xi[tid] = x[tid * L_ + i];
    if (tid >= 32 && tid < 52) wsrow[tid - 32] = ws[i * A_ + (tid - 32)];
    asm volatile("fence.proxy.async.shared::cta;" ::: "memory");
    __syncthreads();

    float acc[4] = {0.f, 0.f, 0.f, 0.f};
    float pair = 0.f, c_acc = 0.f, reg1 = 0.f, reg2 = 0.f;

    if (wid < 5) {
        // ---- Consumers: warp handles j = wid*4..wid*4+3, lane = b ----
        const char* btj0 = smem_raw + wid * 320;    // rows wid*4.. (80 B each)
        const uint2* xpk2 = reinterpret_cast<const uint2*>(xpk);
        const float4* b4all = reinterpret_cast<const float4*>(smem_raw);
        const int cid = wid * 32 + lane;            // 0..159
        int r = 0, ph = 0;
        for (int sidx = 0; sidx < NSTAGE; sidx++) {
            mb_wait_acq(mb0 + r * 16, ph);

            // reg pass: 20 floats/lane (5 x LDS.128), covers 3200 floats/stage
#pragma unroll
            for (int w = 0; w < 5; w++) {
                float4 qv = b4all[r * 800 + cid + w * 160];
                reg1 += fabsf(qv.x); reg2 = fmaf(qv.x, qv.x, reg2);
                reg1 += fabsf(qv.y); reg2 = fmaf(qv.y, qv.y, reg2);
                reg1 += fabsf(qv.z); reg2 = fmaf(qv.z, qv.z, reg2);
                reg1 += fabsf(qv.w); reg2 = fmaf(qv.w, qv.w, reg2);
            }

            const int pbase = q * 64 + sidx * TS;
            if (pbase + TS - 1 > i) {
                const char* bj = btj0 + r * STAGE_BYTES;
                const uint2 u = xpk2[sidx * 32 + lane];
                const uint32_t wv[2] = {u.x, u.y};
                if (pbase > i) {          // ABOVE: all 8 tiles
#pragma unroll
                    for (int k = 0; k < TS; k++) {
                        uint32_t e4 = __byte_perm(wv[k >> 2], 0, 0x4440 | (k & 3));
                        const char* bk = bj + k * 1600 + e4;
                        acc[0] += *reinterpret_cast<const float*>(bk);
                        acc[1] += *reinterpret_cast<const float*>(bk + 80);
                        acc[2] += *reinterpret_cast<const float*>(bk + 160);
                        acc[3] += *reinterpret_cast<const float*>(bk + 240);
                    }
                } else {                  // MIXED
#pragma unroll
                    for (int k = 0; k < TS; k++) {
                        if (pbase + k > i) {
                            uint32_t e4 = __byte_perm(wv[k >> 2], 0, 0x4440 | (k & 3));
                            const char* bk = bj + k * 1600 + e4;
                            acc[0] += *reinterpret_cast<const float*>(bk);
                            acc[1] += *reinterpret_cast<const float*>(bk + 80);
                            acc[2] += *reinterpret_cast<const float*>(bk + 160);
                            acc[3] += *reinterpret_cast<const float*>(bk + 240);
                        }
                    }
                }
            }
            if (lane == 0) MB_ARRIVE(mb0 + r * 16 + 8);
            if (++r == RING) { r = 0; ph ^= 1; }
        }
    } else if (wid == 5) {
        // ---- Pair warp: lane = b, all p of this quarter ----
        const char* bt0 = smem_raw + xi[lane] * 80;
        const uint2* xpk2 = reinterpret_cast<const uint2*>(xpk);
        int r = 0, ph = 0;
        for (int sidx = 0; sidx < NSTAGE; sidx++) {
            mb_wait_acq(mb0 + r * 16, ph);
            const char* bt = bt0 + r * STAGE_BYTES;
            const uint2 u = xpk2[sidx * 32 + lane];
            const uint32_t wv[2] = {u.x, u.y};
#pragma unroll
            for (int k = 0; k < TS; k++) {
                uint32_t e4 = __byte_perm(wv[k >> 2], 0, 0x4440 | (k & 3));
                pair += *reinterpret_cast<const float*>(bt + k * 1600 + e4);
            }
            if (lane == 0) MB_ARRIVE(mb0 + r * 16 + 8);
            if (++r == RING) { r = 0; ph ^= 1; }
        }
    } else if (wid == 6) {
        // ---- Const warp: lanes 0..19, j = lane ----
        int r = 0, ph = 0;
        for (int sidx = 0; sidx < NSTAGE; sidx++) {
            mb_wait_acq(mb0 + r * 16, ph);
            const int pbase = q * 64 + sidx * TS;
            if (lane < 20 && pbase <= i) {
                const float* bf = bufs + r * STAGE_F;
                int tmax = i - pbase;              // t < tmax  <=>  p < i
                int lim = tmax < TS ? tmax : TS;
                for (int t = 0; t < lim; t++) c_acc += bf[t * 400 + lane * 20 + 19];
                if (tmax < TS) c_acc += bf[tmax * 400 + lane * 21];   // diag p==i
            }
            if (lane == 0) MB_ARRIVE(mb0 + r * 16 + 8);
            if (++r == RING) { r = 0; ph ^= 1; }
        }
    } else {
        // ---- Producer (warp 7, lane 0) ----
        if (lane == 0) {
            const char* src = reinterpret_cast<const char*>(wp) +
                              (size_t)i * 409600 + (size_t)q * 102400;
            int r = 0, wr = 0, wph = 0;
            for (int sidx = 0; sidx < NSTAGE; sidx++) {
                if (sidx >= RING) {
                    mb_wait_rlx(mb0 + wr * 16 + 8, wph);
                    if (++wr == RING) { wr = 0; wph ^= 1; }
                }
                MB_EXPECT_TX(mb0 + r * 16, STAGE_BYTES);
                bulk_g2s(bufa + r * STAGE_BYTES, src + (size_t)sidx * STAGE_BYTES,
                         STAGE_BYTES, mb0 + r * 16);
                if (++r == RING) r = 0;
            }
        }
    }

    // ---------------- Per-CTA epilogue: write quarter partials ----------------
    if (wid < 5) {
        float rv = reg1 + reg2;
#pragma unroll
        for (int o = 16; o > 0; o >>= 1) rv += __shfl_down_sync(0xffffffffu, rv, o);
        if (lane == 0) sredr[wid] = rv;
    }
    if (wid == 5) {
        float pv = pair;
#pragma unroll
        for (int o = 16; o > 0; o >>= 1) pv += __shfl_down_sync(0xffffffffu, pv, o);
        if (lane == 0) pairv[0] = pv;
    }
    __syncthreads();

    float* lg = &g_lg[i][q][0];
    if (wid < 5) {
#pragma unroll
        for (int t = 0; t < 4; t++) lg[lane * 20 + wid * 4 + t] = acc[t];
    }
    if (wid == 6 && lane < 20) lg[640 + lane] = c_acc;
    if (tid == 224) {
        float rs = 0.f;
        for (int w = 0; w < 5; w++) rs += sredr[w];
        lg[660] = pairv[0];
        lg[661] = rs;
    }
    __threadfence();
    __syncthreads();

    // ---- Gate 1: 4th CTA of row i combines ----
    if (tid == 0) flags[0] = (atomicAdd(&g_icount[i], 1u) == 3u) ? 1 : 0;
    __syncthreads();
    if (!flags[0]) return;
    __threadfence();

    if (tid < 20) {
        cstsc[tid] = g_lg[i][0][640 + tid] + g_lg[i][1][640 + tid] +
                     g_lg[i][2][640 + tid] + g_lg[i][3][640 + tid];
    }
    __syncthreads();
    for (int n = tid; n < 640; n += NTHR) {
        float sv = g_lg[i][0][n] + g_lg[i][1][n] + g_lg[i][2][n] + g_lg[i][3][n];
        int bb = n / 20, jj = n - bb * 20;
        bufs[bb * 21 + jj] = sv + cstsc[jj] + wsrow[jj];
    }
    if (tid == 200)
        g_res[i][1] = (double)g_lg[i][0][660] + (double)g_lg[i][1][660] +
                      (double)g_lg[i][2][660] + (double)g_lg[i][3][660];
    if (tid == 201)
        g_res[i][2] = (double)g_lg[i][0][661] + (double)g_lg[i][1][661] +
                      (double)g_lg[i][2][661] + (double)g_lg[i][3][661];
    __syncthreads();

    if (tid < 32) {       // lse per b, minus single
        const float* row = &bufs[tid * 21];
        float m = row[0];
#pragma unroll
        for (int jj = 1; jj < A_; jj++) m = fmaxf(m, row[jj]);
        float se = 0.f;
#pragma unroll
        for (int jj = 0; jj < A_; jj++) se += __expf(row[jj] - m);
        float lse = m + __logf(se);
        double val = (double)lse - (double)wsrow[xi[tid]];
#pragma unroll
        for (int o = 16; o > 0; o >>= 1) val += __shfl_down_sync(0xffffffffu, val, o);
        if (tid == 0) g_res[i][0] = val;
    }
    __syncthreads();
    if (tid == 0) g_icount[i] = 0;   // self-reset for graph replay
    __threadfence();
    __syncthreads();

    // ---- Gate 2: last combiner does deterministic final reduction ----
    if (tid == 0) flags[1] = (atomicAdd(&g_bcount, 1u) == (unsigned)(L_ - 1)) ? 1 : 0;
    __syncthreads();
    if (!flags[1]) return;
    __threadfence();

    double LS = 0.0, PA = 0.0, RP = 0.0, RS = 0.0;
    if (tid < L_) { LS = g_res[tid][0]; PA = g_res[tid][1]; RP = g_res[tid][2]; }
    for (int n = tid; n < L_ * A_; n += NTHR) {
        float w = ws[n];
        RS += (double)fabsf(w) + (double)w * (double)w;
    }
    double* dred = reinterpret_cast<double*>(smem_raw + 4096);
#pragma unroll
    for (int o = 16; o > 0; o >>= 1) {
        LS += __shfl_down_sync(0xffffffffu, LS, o);
        PA += __shfl_down_sync(0xffffffffu, PA, o);
        RP += __shfl_down_sync(0xffffffffu, RP, o);
        RS += __shfl_down_sync(0xffffffffu, RS, o);
    }
    if (lane == 0) {
        dred[wid] = LS; dred[8 + wid] = PA; dred[16 + wid] = RP; dred[24 + wid] = RS;
    }
    __syncthreads();
    if (tid == 0) {
        double ls = 0, pa = 0, rp = 0, rs = 0;
        for (int w = 0; w < 8; w++) {
            ls += dred[w]; pa += dred[8 + w]; rp += dred[16 + w]; rs += dred[24 + w];
        }
        // LAMBDA_SINGLE = 1.0, LAMBDA_PAIR = 0.2*(L-1) = 51.0
        out[0] = (float)((ls - pa) / (double)B_ + 1.0 * rs + 51.0 * rp);
        g_bcount = 0;   // self-reset for graph replay
    }
}

extern "C" void kernel_launch(void* const* d_in, const int* in_sizes, int n_in,
                              void* d_out, int out_size) {
    (void)in_sizes; (void)n_in; (void)out_size;
    const int*   x  = (const int*)d_in[0];
    const float* ws = (const float*)d_in[1];
    const float* wp = (const float*)d_in[2];
    float* out = (float*)d_out;

    cudaFuncSetAttribute(mrf_kernel, cudaFuncAttributeMaxDynamicSharedMemorySize, SMEM_BYTES);
    dim3 grid(L_, 4);
    mrf_kernel<<<grid, NTHR, SMEM_BYTES>>>(x, ws, wp, out);
}

// round 15
// speedup vs baseline: 1.1069x; 1.0557x over previous
#include <cuda_runtime.h>
#include <cuda.h>
#include <math.h>
#include <stdint.h>

#define B_ 32
#define L_ 256
#define A_ 20
#define NTHR 736            // 20 consumer warps + producer + pair + const
#define TS 16               // tiles per stage
#define RING 3
#define NSTAGE 16           // 256 tiles / 16
#define STAGE_F 6400
#define STAGE_BYTES 25600

__device__ double g_res[L_][3];          // per-i {lse_sum, pair_sum, reg_sum}
__device__ unsigned int g_bcount = 0;    // reset by last block each launch

// smem layout (bytes):
//   0     .. 76800  ring data (3 x 25600), row-major tiles
//   76800 .. 84992  xpk uint32[16 sidx][32 b][4 g]: bytes 4*x[b][p]
//   84992 .. 85120  xi[32]
//   85120 .. 85200  wsrow[20]
//   85200 .. 85280  csts[20]
//   85280 .. 85360  sredr[20]
//   85360 .. 85408  mbarriers per r (stride 16): full +0, empty +8
//   85408 .. 85412  amLast
// epilogue reuse: lgbuf f32[32*21] @0, dred double[4*32] @byte 4096
#define SMEM_BYTES 85424
#define MB_OFF 85360

__device__ __forceinline__ uint32_t smem_u32(const void* p) {
    uint32_t a;
    asm("{ .reg .u64 t; cvta.to.shared.u64 t, %1; cvt.u32.u64 %0, t; }" : "=r"(a) : "l"(p));
    return a;
}
#define MB_INIT(addr, cnt) \
    asm volatile("mbarrier.init.shared.b64 [%0], %1;" :: "r"(addr), "r"(cnt) : "memory")
#define MB_EXPECT_TX(addr, bytes) \
    asm volatile("mbarrier.arrive.expect_tx.shared.b64 _, [%0], %1;" :: "r"(addr), "r"(bytes) : "memory")
#define MB_ARRIVE(addr) \
    asm volatile("mbarrier.arrive.shared.b64 _, [%0];" :: "r"(addr) : "memory")

__device__ __forceinline__ void mb_wait_acq(uint32_t mbar, uint32_t parity) {
    asm volatile(
        "{\n\t.reg .pred P;\n\t"
        "WL_%=:\n\t"
        "mbarrier.try_wait.parity.acquire.cta.shared::cta.b64 P, [%0], %1, 0x989680;\n\t"
        "@P bra.uni WD_%=;\n\t"
        "bra.uni WL_%=;\n\t"
        "WD_%=:\n\t}"
        :: "r"(mbar), "r"(parity) : "memory");
}
__device__ __forceinline__ void mb_wait_rlx(uint32_t mbar, uint32_t parity) {
    asm volatile(
        "{\n\t.reg .pred P;\n\t"
        "WL_%=:\n\t"
        "mbarrier.try_wait.parity.relaxed.cta.shared::cta.b64 P, [%0], %1, 0x989680;\n\t"
        "@P bra.uni WD_%=;\n\t"
        "bra.uni WL_%=;\n\t"
        "WD_%=:\n\t}"
        :: "r"(mbar), "r"(parity) : "memory");
}

__global__ __launch_bounds__(NTHR, 2) void mrf_kernel(const int* __restrict__ x,
                                                      const float* __restrict__ ws,
                                                      float* __restrict__ out,
                                                      const __grid_constant__ CUtensorMap tmap) {
    extern __shared__ char smem_raw[];
    float*        bufs  = reinterpret_cast<float*>(smem_raw);
    uint32_t*     xpk   = reinterpret_cast<uint32_t*>(smem_raw + 76800);
    int*          xi    = reinterpret_cast<int*>(smem_raw + 84992);
    float*        wsrow = reinterpret_cast<float*>(smem_raw + 85120);
    float*        csts  = reinterpret_cast<float*>(smem_raw + 85200);
    float*        sredr = reinterpret_cast<float*>(smem_raw + 85280);
    int*          amLast= reinterpret_cast<int*>(smem_raw + 85408);
    const uint32_t mb0  = smem_u32(smem_raw + MB_OFF);
    const uint32_t bufa = smem_u32(smem_raw);

    const int i    = blockIdx.x;
    const int tid  = threadIdx.x;
    const int wid  = tid >> 5;
    const int lane = tid & 31;

    // full: tx-based (count 1). empty: 22 arrivals (20 consumers + pair + const).
    if (tid == 0) {
        for (int r = 0; r < RING; r++) {
            MB_INIT(mb0 + r * 16, 1);
            MB_INIT(mb0 + r * 16 + 8, 22);
        }
    }

    // Pack x transpose, pre-scaled by 4: xpk[sidx*128 + lane*4 + w] holds bytes
    // 4*x[b=lane][p = sidx*16 + 4w .. +3]
    const int4* x4 = reinterpret_cast<const int4*>(x);
    for (int n = tid; n < 2048; n += NTHR) {
        int sidx = n >> 7, rem = n & 127;
        int b = rem >> 2, w = rem & 3;
        int4 q = x4[b * 64 + sidx * 4 + w];
        xpk[n] = (uint32_t)(q.x << 2) | ((uint32_t)(q.y << 2) << 8) |
                 ((uint32_t)(q.z << 2) << 16) | ((uint32_t)(q.w << 2) << 24);
    }
    if (tid < B_) xi[tid] = x[tid * L_ + i];
    if (tid >= 32 && tid < 52) wsrow[tid - 32] = ws[i * A_ + (tid - 32)];
    asm volatile("fence.proxy.async.shared::cta;" ::: "memory");
    __syncthreads();

    float acc = 0.f, pair = 0.f, c_acc = 0.f, reg1 = 0.f, reg2 = 0.f;

    if (wid < 20) {
        // ---- Consumers: warp = j, lane = b; gather p>i + reg pass ----
        const char* btj0 = smem_raw + wid * 80;   // + r*STAGE_BYTES later
        const uint4* xpk4 = reinterpret_cast<const uint4*>(xpk);
        const float4* b4all = reinterpret_cast<const float4*>(smem_raw);
        const float2* b2all = reinterpret_cast<const float2*>(smem_raw);
        int r = 0, ph = 0;
        for (int sidx = 0; sidx < NSTAGE; sidx++) {
            mb_wait_acq(mb0 + r * 16, ph);

            // reg pass: 10 floats/lane (2 x LDS.128 + 1 x LDS.64)
            {
                float4 q1 = b4all[r * 1600 + tid];
                float4 q2 = b4all[r * 1600 + 640 + tid];
                float2 t2 = b2all[r * 3200 + 2560 + tid];
                reg1 += fabsf(q1.x); reg2 = fmaf(q1.x, q1.x, reg2);
                reg1 += fabsf(q1.y); reg2 = fmaf(q1.y, q1.y, reg2);
                reg1 += fabsf(q1.z); reg2 = fmaf(q1.z, q1.z, reg2);
                reg1 += fabsf(q1.w); reg2 = fmaf(q1.w, q1.w, reg2);
                reg1 += fabsf(q2.x); reg2 = fmaf(q2.x, q2.x, reg2);
                reg1 += fabsf(q2.y); reg2 = fmaf(q2.y, q2.y, reg2);
                reg1 += fabsf(q2.z); reg2 = fmaf(q2.z, q2.z, reg2);
                reg1 += fabsf(q2.w); reg2 = fmaf(q2.w, q2.w, reg2);
                reg1 += fabsf(t2.x); reg2 = fmaf(t2.x, t2.x, reg2);
                reg1 += fabsf(t2.y); reg2 = fmaf(t2.y, t2.y, reg2);
            }

            const int pbase = sidx * TS;
            if (pbase + TS - 1 > i) {
                const char* btj = btj0 + r * STAGE_BYTES;
                const uint4 u = xpk4[sidx * 32 + lane];
                const uint32_t wv[4] = {u.x, u.y, u.z, u.w};
                if (pbase > i) {          // ABOVE: all 16 tiles
#pragma unroll
                    for (int k = 0; k < TS; k++) {
                        uint32_t e4 = __byte_perm(wv[k >> 2], 0, 0x4440 | (k & 3));
                        acc += *reinterpret_cast<const float*>(btj + k * 1600 + e4);
                    }
                } else {                  // MIXED
#pragma unroll
                    for (int k = 0; k < TS; k++) {
                        uint32_t e4 = __byte_perm(wv[k >> 2], 0, 0x4440 | (k & 3));
                        if (pbase + k > i)
                            acc += *reinterpret_cast<const float*>(btj + k * 1600 + e4);
                    }
                }
            }
            if (lane == 0) MB_ARRIVE(mb0 + r * 16 + 8);
            if (++r == RING) { r = 0; ph ^= 1; }
        }
    } else if (wid == 20) {
        // ---- Producer (lane 0): tensor TMA (UTMALDG), one 25.6 KB box/stage ----
        if (lane == 0) {
            int r = 0, wr = 0, wph = 0;
            for (int sidx = 0; sidx < NSTAGE; sidx++) {
                if (sidx >= RING) {
                    mb_wait_rlx(mb0 + wr * 16 + 8, wph);
                    if (++wr == RING) { wr = 0; wph ^= 1; }
                }
                MB_EXPECT_TX(mb0 + r * 16, STAGE_BYTES);
                asm volatile(
                    "cp.async.bulk.tensor.3d.shared::cta.global.tile.mbarrier::complete_tx::bytes "
                    "[%0], [%1, {%2, %3, %4}], [%5];"
                    :: "r"(bufa + r * STAGE_BYTES), "l"(&tmap),
                       "r"(0), "r"(sidx * 100), "r"(i),
                       "r"(mb0 + r * 16) : "memory");
                if (++r == RING) r = 0;
            }
        }
    } else if (wid == 21) {
        // ---- Pair warp: lane = b, all p ----
        const char* bt0 = smem_raw + xi[lane] * 80;
        const uint4* xpk4 = reinterpret_cast<const uint4*>(xpk);
        int r = 0, ph = 0;
        for (int sidx = 0; sidx < NSTAGE; sidx++) {
            mb_wait_acq(mb0 + r * 16, ph);
            const char* bt = bt0 + r * STAGE_BYTES;
            const uint4 u = xpk4[sidx * 32 + lane];
            const uint32_t wv[4] = {u.x, u.y, u.z, u.w};
#pragma unroll
            for (int k = 0; k < TS; k++) {
                uint32_t e4 = __byte_perm(wv[k >> 2], 0, 0x4440 | (k & 3));
                pair += *reinterpret_cast<const float*>(bt + k * 1600 + e4);
            }
            if (lane == 0) MB_ARRIVE(mb0 + r * 16 + 8);
            if (++r == RING) { r = 0; ph ^= 1; }
        }
    } else {
        // ---- Const warp: lanes 0..19, j = lane ----
        const int j20 = lane * 20;
        int r = 0, ph = 0;
        for (int sidx = 0; sidx < NSTAGE; sidx++) {
            mb_wait_acq(mb0 + r * 16, ph);
            const int pbase = sidx * TS;
            if (lane < 20 && pbase <= i) {
                const float* bt = bufs + r * STAGE_F;
                int tmax = i - pbase;              // t < tmax  <=>  p < i
                int lim = tmax < TS ? tmax : TS;
                for (int t = 0; t < lim; t++) c_acc += bt[t * 400 + j20 + 19];
                if (tmax < TS) c_acc += bt[tmax * 400 + j20 + lane];   // diag p==i
            }
            if (lane == 0) MB_ARRIVE(mb0 + r * 16 + 8);
            if (++r == RING) { r = 0; ph ^= 1; }
        }
    }

    // ---------------- Epilogue ----------------
    if (wid == 22 && lane < 20) csts[lane] = c_acc;
    if (wid < 20) {
        float rv = reg1 + reg2;
#pragma unroll
        for (int o = 16; o > 0; o >>= 1) rv += __shfl_down_sync(0xffffffffu, rv, o);
        if (lane == 0) sredr[wid] = rv;
    }
    if (wid == 21) {
        double pv = (double)pair;
#pragma unroll
        for (int o = 16; o > 0; o >>= 1) pv += __shfl_down_sync(0xffffffffu, pv, o);
        if (lane == 0) g_res[i][1] = pv;
    }
    __syncthreads();

    if (wid < 20) bufs[lane * 21 + wid] = acc + csts[wid] + wsrow[wid];  // lgbuf[b*21+j]
    __syncthreads();

    if (tid < 32) {       // lse per b, minus single
        const float* row = &bufs[tid * 21];
        float m = row[0];
#pragma unroll
        for (int j = 1; j < A_; j++) m = fmaxf(m, row[j]);
        float se = 0.f;
#pragma unroll
        for (int j = 0; j < A_; j++) se += __expf(row[j] - m);
        float lse = m + __logf(se);
        double val = (double)lse - (double)wsrow[xi[tid]];
#pragma unroll
        for (int o = 16; o > 0; o >>= 1) val += __shfl_down_sync(0xffffffffu, val, o);
        if (tid == 0) g_res[i][0] = val;
    } else if (tid < 64) {   // reg sum over 20 warps
        double rv = (lane < 20) ? (double)sredr[lane] : 0.0;
#pragma unroll
        for (int o = 16; o > 0; o >>= 1) rv += __shfl_down_sync(0xffffffffu, rv, o);
        if (lane == 0) g_res[i][2] = rv;
    }
    __syncthreads();

    // ---------------- Fused deterministic final reduction (last CTA) ----------------
    if (tid == 0) {
        __threadfence();
        *amLast = (atomicAdd(&g_bcount, 1u) == (unsigned)(gridDim.x - 1)) ? 1 : 0;
    }
    __syncthreads();
    if (!*amLast) return;
    __threadfence();

    double LS = 0.0, PA = 0.0, RP = 0.0, RS = 0.0;
    if (tid < L_) { LS = g_res[tid][0]; PA = g_res[tid][1]; RP = g_res[tid][2]; }
    for (int n = tid; n < L_ * A_; n += NTHR) {
        float w = ws[n];
        RS += (double)fabsf(w) + (double)w * (double)w;
    }
    double* dred = reinterpret_cast<double*>(smem_raw + 4096);
#pragma unroll
    for (int o = 16; o > 0; o >>= 1) {
        LS += __shfl_down_sync(0xffffffffu, LS, o);
        PA += __shfl_down_sync(0xffffffffu, PA, o);
        RP += __shfl_down_sync(0xffffffffu, RP, o);
        RS += __shfl_down_sync(0xffffffffu, RS, o);
    }
    if (lane == 0) {
        dred[wid] = LS; dred[32 + wid] = PA; dred[64 + wid] = RP; dred[96 + wid] = RS;
    }
    __syncthreads();
    if (tid == 0) {
        double ls = 0, pa = 0, rp = 0, rs = 0;
        for (int w = 0; w < 23; w++) {
            ls += dred[w]; pa += dred[32 + w]; rp += dred[64 + w]; rs += dred[96 + w];
        }
        // LAMBDA_SINGLE = 1.0, LAMBDA_PAIR = 0.2*(L-1) = 51.0
        out[0] = (float)((ls - pa) / (double)B_ + 1.0 * rs + 51.0 * rp);
        g_bcount = 0;   // self-reset for graph replay
    }
}

typedef CUresult (*EncodeFn)(CUtensorMap*, CUtensorMapDataType, cuuint32_t, void*,
                             const cuuint64_t*, const cuuint64_t*,
                             const cuuint32_t*, const cuuint32_t*,
                             CUtensorMapInterleave, CUtensorMapSwizzle,
                             CUtensorMapL2promotion, CUtensorMapFloatOOBfill);

extern "C" void kernel_launch(void* const* d_in, const int* in_sizes, int n_in,
                              void* d_out, int out_size) {
    (void)in_sizes; (void)n_in; (void)out_size;
    const int*   x  = (const int*)d_in[0];
    const float* ws = (const float*)d_in[1];
    const float* wp = (const float*)d_in[2];
    float* out = (float*)d_out;

    // Build tensormap on host (pure CPU driver call; no allocation; graph-safe).
    static CUtensorMap tmap;
    void* fn = nullptr;
    cudaDriverEntryPointQueryResult qst;
    cudaGetDriverEntryPointByVersion("cuTensorMapEncodeTiled", &fn, 12000,
                                     cudaEnableDefault, &qst);
    EncodeFn enc = (EncodeFn)fn;
    cuuint64_t dims[3]    = {256, 1600, 256};        // [bytes, chunks, i-rows]
    cuuint64_t strides[2] = {256, 409600};           // bytes
    cuuint32_t box[3]     = {256, 100, 1};           // 25.6 KB per load
    cuuint32_t es[3]      = {1, 1, 1};
    enc(&tmap, CU_TENSOR_MAP_DATA_TYPE_UINT8, 3, (void*)wp,
        dims, strides, box, es,
        CU_TENSOR_MAP_INTERLEAVE_NONE, CU_TENSOR_MAP_SWIZZLE_NONE,
        CU_TENSOR_MAP_L2_PROMOTION_L2_128B, CU_TENSOR_MAP_FLOAT_OOB_FILL_NONE);

    cudaFuncSetAttribute(mrf_kernel, cudaFuncAttributeMaxDynamicSharedMemorySize, SMEM_BYTES);
    mrf_kernel<<<L_, NTHR, SMEM_BYTES>>>(x, ws, out, tmap);
}